// round 6
// baseline (speedup 1.0000x reference)
#include <cuda_runtime.h>
#include <cuda_fp16.h>

// MVF_Dyn: trilinear-upsampled motion-field warp of a 2-channel 3D image.
//   image:       [1,1,48,256,256,2] f32
//   mvf_kernels: [1,4,3,48,128,128] f32
//   out:         [1,5,48,256,256,2] f32  (phase 0 = copy of image, 1..4 warped)
//
// Round-6: keep the round-5 z+x-paired fp16 layout (2 LDG.128 per trilinear
// sample = structural floor), but give each thread 4 samples (w-pair x 2 h
// rows) -> 8 independent gathers in flight, branch-free OOB handling via
// zero weights on clamped addresses, shared mvf staging for both rows.

namespace {

constexpr int Dv = 48, Hv = 256, Wv = 256;
constexpr int HM = 128, WM = 128;
constexpr int PH = 4;

// 48*256*256 * 16B = 50.3 MB scratch.
__device__ uint4 g_pairs[Dv * Hv * Wv];

__device__ __forceinline__ unsigned pack_h2(float a, float b) {
  __half2 h = __floats2half2_rn(a, b);
  return *reinterpret_cast<unsigned*>(&h);
}

// Builds g_pairs (fp16, z+x paired) and writes the phase-0 fp32 copy.
__global__ void __launch_bounds__(256)
prep_kernel(const float2* __restrict__ img, float2* __restrict__ out0) {
  const int y = blockIdx.x & (Hv - 1);
  const int z = blockIdx.x >> 8;       // Hv = 256
  const int x = threadIdx.x;           // 0..255
  __shared__ float2 srow[2][Wv + 1];
  const size_t base0 = ((size_t)z * Hv + y) * Wv;
  const float2 v0 = img[base0 + x];
  float2 v1 = make_float2(0.f, 0.f);
  if (z + 1 < Dv) v1 = img[base0 + (size_t)Hv * Wv + x];
  srow[0][x] = v0;
  srow[1][x] = v1;
  if (x == 0) {
    srow[0][Wv] = make_float2(0.f, 0.f);  // zero pad for x0 == Wv-1
    srow[1][Wv] = make_float2(0.f, 0.f);
  }
  __syncthreads();
  const float2 n0 = srow[0][x + 1];
  const float2 n1 = srow[1][x + 1];
  uint4 q;
  q.x = pack_h2(v0.x, v0.y);  // (z,   x)
  q.y = pack_h2(n0.x, n0.y);  // (z,   x+1)
  q.z = pack_h2(v1.x, v1.y);  // (z+1, x)
  q.w = pack_h2(n1.x, n1.y);  // (z+1, x+1)
  g_pairs[base0 + x] = q;
  out0[base0 + x] = v0;        // phase-0 copy (exact fp32)
}

__device__ __forceinline__ float2 h2f(unsigned u) {
  return __half22float2(*reinterpret_cast<__half2*>(&u));
}

// Branch-free trilinear sample with zero padding; z+x paired fp16 layout.
// OOB taps get zero weight on a clamped (always-valid) address.
__device__ __forceinline__ float2 sample_one(float z, float y, float x) {
  const int z0 = __float2int_rd(z);
  const int y0 = __float2int_rd(y);
  const int x0 = __float2int_rd(x);
  const float wz = z - (float)z0, wy = y - (float)y0, wx = x - (float)x0;

  const bool xin = (unsigned)x0 < (unsigned)Wv;
  const int xc = xin ? x0 : 0;
  const float wa = xin ? (1.f - wx) : ((x0 == -1) ? wx : 0.f);  // x0 half
  const float wb = xin ? wx : 0.f;                              // x0+1 half

  const bool zin = (unsigned)z0 < (unsigned)Dv;
  const int zc = zin ? z0 : 0;
  const float za = zin ? (1.f - wz) : ((z0 == -1) ? wz : 0.f);  // z lo half
  const float zb = zin ? wz : 0.f;                              // z hi half

  const int y0c = min(max(y0, 0), Hv - 1);
  const int y1c = min(max(y0 + 1, 0), Hv - 1);
  const float wy0 = ((unsigned)y0 < (unsigned)Hv) ? (1.f - wy) : 0.f;
  const float wy1 = ((unsigned)(y0 + 1) < (unsigned)Hv) ? wy : 0.f;

  const uint4* base = g_pairs + (size_t)zc * (Hv * Wv);
  const uint4 qa = __ldg(base + y0c * Wv + xc);
  const uint4 qb = __ldg(base + y1c * Wv + xc);

  float2 r;
  {
    float2 a0 = h2f(qa.x), a1 = h2f(qa.y), b0 = h2f(qa.z), b1 = h2f(qa.w);
    float t0x = fmaf(za, a0.x, zb * b0.x), t0y = fmaf(za, a0.y, zb * b0.y);
    float t1x = fmaf(za, a1.x, zb * b1.x), t1y = fmaf(za, a1.y, zb * b1.y);
    r.x = wy0 * fmaf(wa, t0x, wb * t1x);
    r.y = wy0 * fmaf(wa, t0y, wb * t1y);
  }
  {
    float2 a0 = h2f(qb.x), a1 = h2f(qb.y), b0 = h2f(qb.z), b1 = h2f(qb.w);
    float t0x = fmaf(za, a0.x, zb * b0.x), t0y = fmaf(za, a0.y, zb * b0.y);
    float t1x = fmaf(za, a1.x, zb * b1.x), t1y = fmaf(za, a1.y, zb * b1.y);
    r.x = fmaf(wy1, fmaf(wa, t0x, wb * t1x), r.x);
    r.y = fmaf(wy1, fmaf(wa, t0y, wb * t1y), r.y);
  }
  return r;
}

// Block: rows (h0, h0+1) of one (d, p). Thread k handles 4 samples:
// (row0, w=2k), (row0, 2k+1), (row1, 2k), (row1, 2k+1) -> 8 gathers in flight.
// jax.image.resize 'trilinear' 2x (half-pixel, edge-renormalized):
//   even out idx 2j   -> taps (j-1, j)  weights (0.25, 0.75), clamp at edges
//   odd  out idx 2j+1 -> taps (j, j+1)  weights (0.75, 0.25), clamp at edges
// Depth is identity.
__global__ void __launch_bounds__(128)
warp_kernel(const float* __restrict__ mvf,    // [4][3][48][128][128]
            float4* __restrict__ out) {       // output as float4 (w pairs)
  const int h0 = blockIdx.x * 2;
  const int d = blockIdx.y;
  const int p = blockIdx.z;
  const int k = threadIdx.x;  // 0..127
  const int a = h0 >> 1;

  // Stage mvf source rows a-1, a, a+1 (clamped) for all 3 channels.
  __shared__ float s[3][3][WM];
  for (int i = k; i < 3 * 3 * WM; i += 128) {
    int x = i & (WM - 1);
    int ri = (i >> 7) % 3;
    int c = (i >> 7) / 3;
    int jr = min(max(a - 1 + ri, 0), HM - 1);
    s[c][ri][x] = __ldg(mvf + ((size_t)(p * 3 + c) * Dv + d) * (size_t)(HM * WM)
                        + jr * WM + x);
  }
  __syncthreads();

  const int km1 = max(k - 1, 0);
  const int kp1 = min(k + 1, WM - 1);

  // mA: (row h0, even w)  mB: (row h0, odd w)
  // mC: (row h0+1, even)  mD: (row h0+1, odd)
  float mA[3], mB[3], mC[3], mD[3];
#pragma unroll
  for (int c = 0; c < 3; c++) {
    float a0 = s[c][0][km1], b0 = s[c][0][k], c0 = s[c][0][kp1];
    float a1 = s[c][1][km1], b1 = s[c][1][k], c1 = s[c][1][kp1];
    float a2 = s[c][2][km1], b2 = s[c][2][k], c2 = s[c][2][kp1];
    float e0 = fmaf(0.25f, a0, 0.75f * b0), o0 = fmaf(0.75f, b0, 0.25f * c0);
    float e1 = fmaf(0.25f, a1, 0.75f * b1), o1 = fmaf(0.75f, b1, 0.25f * c1);
    float e2 = fmaf(0.25f, a2, 0.75f * b2), o2 = fmaf(0.75f, b2, 0.25f * c2);
    // row h0 (even): y-taps (r0, r1), weight 0.75 on r1
    mA[c] = fmaf(0.25f, e0, 0.75f * e1);
    mB[c] = fmaf(0.25f, o0, 0.75f * o1);
    // row h0+1 (odd): y-taps (r1, r2), weight 0.25 on r2
    mC[c] = fmaf(0.75f, e1, 0.25f * e2);
    mD[c] = fmaf(0.75f, o1, 0.25f * o2);
  }

  const float fd = (float)d;
  const float f0 = (float)h0, f1 = (float)(h0 + 1);
  const float xe = (float)(2 * k), xo = (float)(2 * k + 1);

  float2 rA = sample_one(fd + mA[0], f0 + 2.f * mA[1], xe + 2.f * mA[2]);
  float2 rB = sample_one(fd + mB[0], f0 + 2.f * mB[1], xo + 2.f * mB[2]);
  float2 rC = sample_one(fd + mC[0], f1 + 2.f * mC[1], xe + 2.f * mC[2]);
  float2 rD = sample_one(fd + mD[0], f1 + 2.f * mD[1], xo + 2.f * mD[2]);

  size_t base = (((size_t)((p + 1) * Dv + d) * Hv + h0) * (Wv / 2)) + k;
  out[base] = make_float4(rA.x, rA.y, rB.x, rB.y);
  out[base + (Wv / 2)] = make_float4(rC.x, rC.y, rD.x, rD.y);
}

}  // namespace

extern "C" void kernel_launch(void* const* d_in, const int* in_sizes, int n_in,
                              void* d_out, int out_size) {
  const float* image = (const float*)d_in[0];
  const float* mvf   = (const float*)d_in[1];
  // Defensive: identify inputs by size (image has 48*256*256*2 = 6291456 elems).
  if (n_in >= 2 && in_sizes[0] != Dv * Hv * Wv * 2) {
    const float* t = image; image = mvf; mvf = t;
  }

  // Build z+x paired fp16 layout + phase-0 copy.
  prep_kernel<<<Dv * Hv, Wv>>>((const float2*)image, (float2*)d_out);

  // Phases 1..4: warp. 2 output rows per block.
  dim3 grid(Hv / 2, Dv, PH);
  warp_kernel<<<grid, 128>>>(mvf, (float4*)d_out);
}

// round 7
// speedup vs baseline: 1.1346x; 1.1346x over previous
#include <cuda_runtime.h>
#include <cuda_fp16.h>

// MVF_Dyn: trilinear-upsampled motion-field warp of a 2-channel 3D image.
//   image:       [1,1,48,256,256,2] f32
//   mvf_kernels: [1,4,3,48,128,128] f32
//   out:         [1,5,48,256,256,2] f32  (phase 0 = copy of image, 1..4 warped)
//
// Round-7: round-5 sampler economics (early-out OOB, predicated y-loop,
// alu~24%) + round-6 amortization (2 rows/block, mvf staged once) without its
// ALU bill: 256-thread blocks (thread = (row, w-pair), 2 samples / 4 LDG.128
// each), unrolled div/mod-free staging, 32-bit gather indices.

namespace {

constexpr int Dv = 48, Hv = 256, Wv = 256;
constexpr int HM = 128, WM = 128;
constexpr int PH = 4;

// 48*256*256 * 16B = 50.3 MB scratch (z+x paired fp16).
__device__ uint4 g_pairs[Dv * Hv * Wv];

__device__ __forceinline__ unsigned pack_h2(float a, float b) {
  __half2 h = __floats2half2_rn(a, b);
  return *reinterpret_cast<unsigned*>(&h);
}

// Builds g_pairs (fp16, z+x paired) and writes the phase-0 fp32 copy.
__global__ void __launch_bounds__(256)
prep_kernel(const float2* __restrict__ img, float2* __restrict__ out0) {
  const int y = blockIdx.x & (Hv - 1);
  const int z = blockIdx.x >> 8;       // Hv = 256
  const int x = threadIdx.x;           // 0..255
  __shared__ float2 srow[2][Wv + 1];
  const size_t base0 = ((size_t)z * Hv + y) * Wv;
  const float2 v0 = img[base0 + x];
  float2 v1 = make_float2(0.f, 0.f);
  if (z + 1 < Dv) v1 = img[base0 + (size_t)Hv * Wv + x];
  srow[0][x] = v0;
  srow[1][x] = v1;
  if (x == 0) {
    srow[0][Wv] = make_float2(0.f, 0.f);  // zero pad for x0 == Wv-1
    srow[1][Wv] = make_float2(0.f, 0.f);
  }
  __syncthreads();
  const float2 n0 = srow[0][x + 1];
  const float2 n1 = srow[1][x + 1];
  uint4 q;
  q.x = pack_h2(v0.x, v0.y);  // (z,   x)
  q.y = pack_h2(n0.x, n0.y);  // (z,   x+1)
  q.z = pack_h2(v1.x, v1.y);  // (z+1, x)
  q.w = pack_h2(n1.x, n1.y);  // (z+1, x+1)
  g_pairs[base0 + x] = q;
  out0[base0 + x] = v0;        // phase-0 copy (exact fp32)
}

__device__ __forceinline__ float2 h2f(unsigned u) {
  return __half22float2(*reinterpret_cast<__half2*>(&u));
}

// Trilinear sample with zero padding; z+x paired fp16 layout; fp32 math.
// Round-5 style: early-out on fully-OOB x/z (rare), predicated y taps.
__device__ __forceinline__ float2 sample_one(float z, float y, float x) {
  const int z0 = __float2int_rd(z);
  const int y0 = __float2int_rd(y);
  const int x0 = __float2int_rd(x);
  const float wz = z - (float)z0, wy = y - (float)y0, wx = x - (float)x0;

  const bool xin = (unsigned)x0 < (unsigned)Wv;
  if (!xin && x0 != -1) return make_float2(0.f, 0.f);
  const int xc = xin ? x0 : 0;
  const float wa = xin ? (1.f - wx) : wx;   // x0 half (x0==-1: tap x=0 w/ wx)
  const float wb = xin ? wx : 0.f;          // x0+1 half

  const bool zin = (unsigned)z0 < (unsigned)Dv;
  if (!zin && z0 != -1) return make_float2(0.f, 0.f);
  const int zc = zin ? z0 : 0;
  const float za = zin ? (1.f - wz) : wz;   // z lo half
  const float zb = zin ? wz : 0.f;          // z hi half

  const int base = zc * (Hv * Wv) + xc;     // 32-bit index
  float ax = 0.f, ay = 0.f;
#pragma unroll
  for (int dy = 0; dy < 2; dy++) {
    const int yi = y0 + dy;
    if ((unsigned)yi >= (unsigned)Hv) continue;
    const float wyy = dy ? wy : 1.f - wy;
    const uint4 q = __ldg(&g_pairs[base + yi * Wv]);
    const float2 a0 = h2f(q.x);  // (z0,   x0)
    const float2 a1 = h2f(q.y);  // (z0,   x1)
    const float2 b0 = h2f(q.z);  // (z0+1, x0)
    const float2 b1 = h2f(q.w);  // (z0+1, x1)
    const float t0x = fmaf(za, a0.x, zb * b0.x), t0y = fmaf(za, a0.y, zb * b0.y);
    const float t1x = fmaf(za, a1.x, zb * b1.x), t1y = fmaf(za, a1.y, zb * b1.y);
    ax = fmaf(wyy, fmaf(wa, t0x, wb * t1x), ax);
    ay = fmaf(wyy, fmaf(wa, t0y, wb * t1y), ay);
  }
  return make_float2(ax, ay);
}

// Block: 256 threads = 2 output rows (h0, h0+1) of one (d, p).
// Thread: r = tid>>7 (row), k = tid&127 (w-pair) -> 2 samples, 4 LDG.128s.
// jax.image.resize 'trilinear' 2x (half-pixel, edge-renormalized):
//   even out idx 2j   -> taps (j-1, j)  weights (0.25, 0.75), clamp at edges
//   odd  out idx 2j+1 -> taps (j, j+1)  weights (0.75, 0.25), clamp at edges
// Depth is identity.
__global__ void __launch_bounds__(256)
warp_kernel(const float* __restrict__ mvf,    // [4][3][48][128][128]
            float4* __restrict__ out) {       // output as float4 (w pairs)
  const int h0 = blockIdx.x * 2;
  const int d = blockIdx.y;
  const int p = blockIdx.z;
  const int tid = threadIdx.x;
  const int k = tid & (WM - 1);   // 0..127 w-pair
  const int r = tid >> 7;         // 0..1 output row
  const int a = h0 >> 1;

  // Stage mvf source rows a-1, a, a+1 (clamped) for 3 channels.
  // Threads 0..127 do 9 unrolled loads each; no div/mod.
  __shared__ float s[3][3][WM];
  if (tid < WM) {
    const int r0 = max(a - 1, 0), r1 = a, r2 = min(a + 1, HM - 1);
    const float* pl = mvf + ((size_t)(p * 3) * Dv + d) * (size_t)(HM * WM);
    const int plane = Dv * HM * WM;
#pragma unroll
    for (int c = 0; c < 3; c++) {
      const float* pc = pl + c * plane;
      s[c][0][tid] = __ldg(pc + r0 * WM + tid);
      s[c][1][tid] = __ldg(pc + r1 * WM + tid);
      s[c][2][tid] = __ldg(pc + r2 * WM + tid);
    }
  }
  __syncthreads();

  const int km1 = max(k - 1, 0);
  const int kp1 = min(k + 1, WM - 1);

  // Row r: even row h0 uses y-taps (row0,row1) w/ (0.25,0.75);
  //        odd row h0+1 uses (row1,row2) w/ (0.75,0.25).
  const int ra = r ? 1 : 0, rb = r ? 2 : 1;
  const float tya = r ? 0.75f : 0.25f, tyb = r ? 0.25f : 0.75f;

  float me[3], mo[3];  // upsampled mvf at w=2k (even) and 2k+1 (odd)
#pragma unroll
  for (int c = 0; c < 3; c++) {
    const float aA = s[c][ra][km1], bA = s[c][ra][k], cA = s[c][ra][kp1];
    const float aB = s[c][rb][km1], bB = s[c][rb][k], cB = s[c][rb][kp1];
    const float eA = fmaf(0.25f, aA, 0.75f * bA), oA = fmaf(0.75f, bA, 0.25f * cA);
    const float eB = fmaf(0.25f, aB, 0.75f * bB), oB = fmaf(0.75f, bB, 0.25f * cB);
    me[c] = fmaf(tya, eA, tyb * eB);
    mo[c] = fmaf(tya, oA, tyb * oB);
  }

  const float fd = (float)d;
  const float fh = (float)(h0 + r);
  const float xe = (float)(2 * k), xo = (float)(2 * k + 1);

  const float2 re = sample_one(fd + me[0], fh + 2.f * me[1], xe + 2.f * me[2]);
  const float2 ro = sample_one(fd + mo[0], fh + 2.f * mo[1], xo + 2.f * mo[2]);

  const size_t oidx = (((size_t)((p + 1) * Dv + d) * Hv + (h0 + r)) * (Wv / 2)) + k;
  out[oidx] = make_float4(re.x, re.y, ro.x, ro.y);
}

}  // namespace

extern "C" void kernel_launch(void* const* d_in, const int* in_sizes, int n_in,
                              void* d_out, int out_size) {
  const float* image = (const float*)d_in[0];
  const float* mvf   = (const float*)d_in[1];
  // Defensive: identify inputs by size (image has 48*256*256*2 = 6291456 elems).
  if (n_in >= 2 && in_sizes[0] != Dv * Hv * Wv * 2) {
    const float* t = image; image = mvf; mvf = t;
  }

  // Build z+x paired fp16 layout + phase-0 copy.
  prep_kernel<<<Dv * Hv, Wv>>>((const float2*)image, (float2*)d_out);

  // Phases 1..4: warp. 2 output rows per 256-thread block.
  dim3 grid(Hv / 2, Dv, PH);
  warp_kernel<<<grid, 256>>>(mvf, (float4*)d_out);
}